// round 2
// baseline (speedup 1.0000x reference)
#include <cuda_runtime.h>

// Problem constants
#define BB 2
#define NN 256
#define EE 512
#define HH 150
#define HP 160          // padded H (zero-padded) -> no guards in hot loops
#define TJ 32           // j-tile per block
#define ECH 32          // K-chunk staged in smem
#define NTHREADS 256

// Scratch: hi (+b1) and hj rows, zero-padded to HP. (No cudaMalloc allowed.)
__device__ float g_hi[BB * NN * HP];
__device__ float g_hj[BB * NN * HP];

// ---------------------------------------------------------------------------
// Stage 1: per-row projections  hi = g @ W1a + b1,  hj = g @ W1b
// grid = B*N blocks, HP threads. Tiny (~80 MFMA total).
// ---------------------------------------------------------------------------
__global__ __launch_bounds__(HP) void row_proj_kernel(
    const float* __restrict__ g,
    const float* __restrict__ W1,
    const float* __restrict__ b1)
{
    __shared__ float sg[EE];
    const int row = blockIdx.x;          // b*NN + i
    const int t   = threadIdx.x;         // 0..159
    const float* gr = g + (size_t)row * EE;
    for (int e = t; e < EE; e += HP) sg[e] = gr[e];
    __syncthreads();

    float a1 = 0.f, a2 = 0.f;
    if (t < HH) {
        const float* Wa = W1 + t;                        // rows [0,E)
        const float* Wb = W1 + (size_t)EE * HH + t;      // rows [E,2E)
        #pragma unroll 8
        for (int e = 0; e < EE; e++) {
            float ge = sg[e];
            a1 = fmaf(ge, Wa[(size_t)e * HH], a1);
            a2 = fmaf(ge, Wb[(size_t)e * HH], a2);
        }
        a1 += b1[t];
    }
    g_hi[(size_t)row * HP + t] = (t < HH) ? a1 : 0.f;
    g_hj[(size_t)row * HP + t] = (t < HH) ? a2 : 0.f;
}

// ---------------------------------------------------------------------------
// Stage 2: fused pair kernel.
//   Per block: one (b,i) and 32 j's.
//   GEMM1: C = PG @ W1c   with PG[j,e] = g_i[e]*g_j[e]  (built in smem)
//   h1    = relu(C + hi_row + hj_row)            (bias folded into hi_row)
//   GEMM2: C2 = h1 @ W2 ; h2 = relu(C2 + b2)
//   score = h2 @ W3 + b3 ;  out = (m_i + m_j + score)/3
// Thread tile: 4j x 5h, 256 threads (8 j-groups x 32 h-lanes).
// ---------------------------------------------------------------------------
__global__ __launch_bounds__(NTHREADS) void pair_kernel(
    const float* __restrict__ g,  const float* __restrict__ m,
    const float* __restrict__ W1, const float* __restrict__ W2,
    const float* __restrict__ b2, const float* __restrict__ W3,
    const float* __restrict__ b3, float* __restrict__ out)
{
    __shared__ float sWc[ECH][HP];   // 20480 B : staged weight chunk (W1c / W2)
    __shared__ float sPg[TJ][ECH];   //  4096 B : PG chunk
    __shared__ float sH1[TJ][HP];    // 20480 B : h1 tile
    __shared__ float sGi[EE];        //  2048 B : g_i row
    __shared__ float sB2[HP];        //   640 B
    __shared__ float sW3[HP];        //   640 B   (total 48384 B <= 48KB)

    const int t  = threadIdx.x;
    const int th = t & 31;           // h-lane (warp lane)
    const int tj = t >> 5;           // j-group 0..7 (one warp each)
    const int jt = blockIdx.x;
    const int i  = blockIdx.y;
    const int b  = blockIdx.z;
    const int jbase = jt * TJ;

    const float* gi = g + ((size_t)b * NN + i) * EE;
    for (int e = t; e < EE; e += NTHREADS) sGi[e] = gi[e];
    if (t < HP) {
        sB2[t] = (t < HH) ? b2[t] : 0.f;
        sW3[t] = (t < HH) ? W3[t] : 0.f;
    }

    float acc[4][5];
    #pragma unroll
    for (int jj = 0; jj < 4; jj++)
        #pragma unroll
        for (int r = 0; r < 5; r++) acc[jj][r] = 0.f;

    const float* W1c = W1 + (size_t)2 * EE * HH;          // rows [2E,3E)
    const float* gj0 = g + ((size_t)b * NN + jbase) * EE;

    // ---------------- GEMM1: K = 512 in chunks of ECH ----------------
    for (int e0 = 0; e0 < EE; e0 += ECH) {
        __syncthreads();
        // stage W1c chunk (zero-pad h >= HH)
        for (int idx = t; idx < ECH * HP; idx += NTHREADS) {
            int ee = idx / HP, hh = idx % HP;
            sWc[ee][hh] = (hh < HH) ? W1c[(size_t)(e0 + ee) * HH + hh] : 0.f;
        }
        // build PG chunk: g_j * g_i
        for (int idx = t; idx < TJ * ECH; idx += NTHREADS) {
            int jj = idx / ECH, ee = idx % ECH;
            sPg[jj][ee] = gj0[(size_t)jj * EE + e0 + ee] * sGi[e0 + ee];
        }
        __syncthreads();
        #pragma unroll 8
        for (int e = 0; e < ECH; e++) {
            float a0 = sPg[tj * 4 + 0][e];
            float a1 = sPg[tj * 4 + 1][e];
            float a2 = sPg[tj * 4 + 2][e];
            float a3 = sPg[tj * 4 + 3][e];
            float w[5];
            #pragma unroll
            for (int r = 0; r < 5; r++) w[r] = sWc[e][th + 32 * r];
            #pragma unroll
            for (int r = 0; r < 5; r++) {
                acc[0][r] = fmaf(a0, w[r], acc[0][r]);
                acc[1][r] = fmaf(a1, w[r], acc[1][r]);
                acc[2][r] = fmaf(a2, w[r], acc[2][r]);
                acc[3][r] = fmaf(a3, w[r], acc[3][r]);
            }
        }
    }
    __syncthreads();

    // ---------------- epilogue 1 -> sH1 (relu), reset acc ----------------
    {
        const float* hiRow = g_hi + ((size_t)b * NN + i) * HP;
        #pragma unroll
        for (int jj = 0; jj < 4; jj++) {
            int j = jbase + tj * 4 + jj;
            const float* hjRow = g_hj + ((size_t)b * NN + j) * HP;
            #pragma unroll
            for (int r = 0; r < 5; r++) {
                int h = th + 32 * r;
                float v = acc[jj][r] + hiRow[h] + hjRow[h];
                sH1[tj * 4 + jj][h] = fmaxf(v, 0.f);
                acc[jj][r] = 0.f;
            }
        }
    }

    // ---------------- GEMM2: K = HP (padded, zeros inert) ----------------
    for (int h0 = 0; h0 < HP; h0 += ECH) {
        __syncthreads();
        for (int idx = t; idx < ECH * HP; idx += NTHREADS) {
            int hh = idx / HP, k = idx % HP;
            int h = h0 + hh;
            sWc[hh][k] = (h < HH && k < HH) ? W2[(size_t)h * HH + k] : 0.f;
        }
        __syncthreads();
        #pragma unroll 8
        for (int e = 0; e < ECH; e++) {
            float a0 = sH1[tj * 4 + 0][h0 + e];
            float a1 = sH1[tj * 4 + 1][h0 + e];
            float a2 = sH1[tj * 4 + 2][h0 + e];
            float a3 = sH1[tj * 4 + 3][h0 + e];
            float w[5];
            #pragma unroll
            for (int r = 0; r < 5; r++) w[r] = sWc[e][th + 32 * r];
            #pragma unroll
            for (int r = 0; r < 5; r++) {
                acc[0][r] = fmaf(a0, w[r], acc[0][r]);
                acc[1][r] = fmaf(a1, w[r], acc[1][r]);
                acc[2][r] = fmaf(a2, w[r], acc[2][r]);
                acc[3][r] = fmaf(a3, w[r], acc[3][r]);
            }
        }
    }

    // ---------------- epilogue 2: relu(+b2), dot W3, warp reduce ----------------
    float part[4];
    #pragma unroll
    for (int jj = 0; jj < 4; jj++) {
        float p = 0.f;
        #pragma unroll
        for (int r = 0; r < 5; r++) {
            int k = th + 32 * r;
            float h2 = fmaxf(acc[jj][r] + sB2[k], 0.f);
            p = fmaf(h2, sW3[k], p);
        }
        #pragma unroll
        for (int off = 16; off; off >>= 1)
            p += __shfl_xor_sync(0xffffffffu, p, off);
        part[jj] = p;
    }

    if (th == 0) {
        float bb3 = b3[0];
        float mi  = m[b * NN + i];
        #pragma unroll
        for (int jj = 0; jj < 4; jj++) {
            int j = jbase + tj * 4 + jj;
            out[((size_t)b * NN + i) * NN + j] =
                (mi + m[b * NN + j] + part[jj] + bb3) * (1.0f / 3.0f);
        }
    }
}

// ---------------------------------------------------------------------------
// Harness entry. Inputs (metadata order):
//  0: g (B,N,E) f32   1: m (B,N,1) f32   2: W1 (3E,H) f32   3: b1 (H)
//  4: W2 (H,H)        5: b2 (H)          6: W3 (H,1)        7: b3 (1)
// out: (B,N,N,1) f32
// ---------------------------------------------------------------------------
extern "C" void kernel_launch(void* const* d_in, const int* in_sizes, int n_in,
                              void* d_out, int out_size)
{
    const float* g  = (const float*)d_in[0];
    const float* m  = (const float*)d_in[1];
    const float* W1 = (const float*)d_in[2];
    const float* b1 = (const float*)d_in[3];
    const float* W2 = (const float*)d_in[4];
    const float* b2 = (const float*)d_in[5];
    const float* W3 = (const float*)d_in[6];
    const float* b3 = (const float*)d_in[7];
    float* out = (float*)d_out;

    row_proj_kernel<<<BB * NN, HP>>>(g, W1, b1);

    dim3 grid(NN / TJ, NN, BB);   // (8, 256, 2)
    pair_kernel<<<grid, NTHREADS>>>(g, m, W1, W2, b2, W3, b3, out);
}

// round 3
// speedup vs baseline: 1.6764x; 1.6764x over previous
#include <cuda_runtime.h>

#define BB 2
#define NN 256
#define EE 512
#define HH 150
#define HP 160          // padded H
#define TJ 64           // j-tile per block
#define ECH 32          // K-chunk
#define NTHREADS 256

#define SPG_STRIDE 33   // padded rows: bank-conflict-free across j-groups
#define SH1_STRIDE 164  // even (float2-aligned), distinct banks across j-groups

// Device scratch (no cudaMalloc allowed)
__device__ float g_hi[BB * NN * HP];
__device__ float g_hj[BB * NN * HP];
__device__ float g_W1cP[EE * HP];   // W1c zero-padded to [512][160]
__device__ float g_W2P[HP * HP];    // W2  zero-padded to [160][160]

// ---- packed f32x2 helpers -------------------------------------------------
__device__ __forceinline__ void ffma2(unsigned long long& d,
                                      unsigned long long a,
                                      unsigned long long b) {
    asm("fma.rn.f32x2 %0, %1, %2, %0;" : "+l"(d) : "l"(a), "l"(b));
}
__device__ __forceinline__ unsigned long long dup2(float x) {
    unsigned long long r;
    asm("mov.b64 %0, {%1, %1};" : "=l"(r) : "f"(x));
    return r;
}

// ---------------------------------------------------------------------------
// Prep: zero-pad W1c and W2 into device scratch (runs every launch; tiny)
// ---------------------------------------------------------------------------
__global__ void pad_weights_kernel(const float* __restrict__ W1,
                                   const float* __restrict__ W2)
{
    int idx = blockIdx.x * blockDim.x + threadIdx.x;
    const float* W1c = W1 + (size_t)2 * EE * HH;
    if (idx < EE * HP) {
        int e = idx / HP, h = idx - e * HP;
        g_W1cP[idx] = (h < HH) ? W1c[(size_t)e * HH + h] : 0.f;
    }
    if (idx < HP * HP) {
        int h = idx / HP, k = idx - h * HP;
        g_W2P[idx] = (h < HH && k < HH) ? W2[(size_t)h * HH + k] : 0.f;
    }
}

// ---------------------------------------------------------------------------
// Stage 1: hi = g @ W1a + b1,  hj = g @ W1b   (padded to HP)
// ---------------------------------------------------------------------------
__global__ __launch_bounds__(HP) void row_proj_kernel(
    const float* __restrict__ g,
    const float* __restrict__ W1,
    const float* __restrict__ b1)
{
    __shared__ float sg[EE];
    const int row = blockIdx.x;
    const int t   = threadIdx.x;
    const float* gr = g + (size_t)row * EE;
    for (int e = t; e < EE; e += HP) sg[e] = gr[e];
    __syncthreads();

    float a1 = 0.f, a2 = 0.f;
    if (t < HH) {
        const float* Wa = W1 + t;
        const float* Wb = W1 + (size_t)EE * HH + t;
        #pragma unroll 8
        for (int e = 0; e < EE; e++) {
            float ge = sg[e];
            a1 = fmaf(ge, Wa[(size_t)e * HH], a1);
            a2 = fmaf(ge, Wb[(size_t)e * HH], a2);
        }
        a1 += b1[t];
    }
    g_hi[(size_t)row * HP + t] = (t < HH) ? a1 : 0.f;
    g_hj[(size_t)row * HP + t] = (t < HH) ? a2 : 0.f;
}

// ---------------------------------------------------------------------------
// Stage 2: fused pair kernel, packed f32x2 over h.
// 256 thr = 16 half-warp groups; group owns 4 j's; lane%16 owns 5 h-pairs.
// ---------------------------------------------------------------------------
extern __shared__ float smem[];

__global__ __launch_bounds__(NTHREADS) void pair_kernel(
    const float* __restrict__ g,  const float* __restrict__ m,
    const float* __restrict__ b2, const float* __restrict__ W3,
    const float* __restrict__ b3, float* __restrict__ out)
{
    // smem carve-up
    float* sWc = smem;                         // [ECH*HP]        20480 B
    float* sPg = sWc + ECH * HP;               // [TJ*SPG_STRIDE]  8448 B
    float* sH1 = sPg + TJ * SPG_STRIDE;        // [TJ*SH1_STRIDE] 41984 B
    float* sGi = sH1 + TJ * SH1_STRIDE;        // [EE]             2048 B
    float* sB2 = sGi + EE;                     // [HP]              640 B
    float* sW3 = sB2 + HP;                     // [HP]              640 B

    const int t   = threadIdx.x;
    const int ln  = t & 31;
    const int hl  = ln & 15;                   // h-pair lane 0..15
    const int grp = (t >> 5) * 2 + (ln >> 4);  // j-group 0..15
    const int jbase = blockIdx.x * TJ;
    const int i  = blockIdx.y;
    const int b  = blockIdx.z;

    const float* gi  = g + ((size_t)b * NN + i) * EE;
    const float* gj0 = g + ((size_t)b * NN + jbase) * EE;

    for (int e = t; e < EE; e += NTHREADS) sGi[e] = gi[e];
    if (t < HP) {
        sB2[t] = (t < HH) ? b2[t] : 0.f;
        sW3[t] = (t < HH) ? W3[t] : 0.f;
    }

    unsigned long long acc[4][5];
    #pragma unroll
    for (int jj = 0; jj < 4; jj++)
        #pragma unroll
        for (int r = 0; r < 5; r++) acc[jj][r] = 0ull;

    const int se = t & 31;       // staging: e-lane
    const int sj = t >> 5;       // staging: j-row base

    // ================= GEMM1: K = 512 =================
    for (int e0 = 0; e0 < EE; e0 += ECH) {
        __syncthreads();
        // stage weight chunk: contiguous float4 copy, no ALU
        {
            const float4* src = (const float4*)(g_W1cP + (size_t)e0 * HP);
            float4* dst = (float4*)sWc;
            #pragma unroll
            for (int k = 0; k < 5; k++) dst[t + 256 * k] = src[t + 256 * k];
        }
        // stage PG chunk: sPg[j][e] = g_j[e]*g_i[e], coalesced LDG, cf STS
        {
            float ge = sGi[e0 + se];
            #pragma unroll
            for (int k = 0; k < 8; k++) {
                int j = sj + 8 * k;
                sPg[j * SPG_STRIDE + se] = gj0[(size_t)j * EE + e0 + se] * ge;
            }
        }
        __syncthreads();

        const float* pgRow = sPg + (grp * 4) * SPG_STRIDE;
        #pragma unroll 8
        for (int e = 0; e < ECH; e++) {
            unsigned long long w[5];
            #pragma unroll
            for (int r = 0; r < 5; r++)
                w[r] = *(const unsigned long long*)&sWc[e * HP + 2 * hl + 32 * r];
            #pragma unroll
            for (int jj = 0; jj < 4; jj++) {
                unsigned long long a = dup2(pgRow[jj * SPG_STRIDE + e]);
                #pragma unroll
                for (int r = 0; r < 5; r++) ffma2(acc[jj][r], a, w[r]);
            }
        }
    }
    __syncthreads();

    // ================= epilogue 1 -> sH1 (relu) =================
    {
        const float* hiRow = g_hi + ((size_t)b * NN + i) * HP;
        #pragma unroll
        for (int jj = 0; jj < 4; jj++) {
            int j = grp * 4 + jj;
            const float* hjRow = g_hj + ((size_t)b * NN + jbase + j) * HP;
            #pragma unroll
            for (int r = 0; r < 5; r++) {
                int h = 2 * hl + 32 * r;
                float2 v = *(float2*)&acc[jj][r];
                float2 hi2 = *(const float2*)&hiRow[h];
                float2 hj2 = *(const float2*)&hjRow[h];
                v.x = fmaxf(v.x + hi2.x + hj2.x, 0.f);
                v.y = fmaxf(v.y + hi2.y + hj2.y, 0.f);
                *(float2*)&sH1[j * SH1_STRIDE + h] = v;
                acc[jj][r] = 0ull;
            }
        }
    }

    // ================= GEMM2: K = HP =================
    for (int h0 = 0; h0 < HP; h0 += ECH) {
        __syncthreads();
        {
            const float4* src = (const float4*)(g_W2P + (size_t)h0 * HP);
            float4* dst = (float4*)sWc;
            #pragma unroll
            for (int k = 0; k < 5; k++) dst[t + 256 * k] = src[t + 256 * k];
        }
        __syncthreads();

        const float* h1Row = sH1 + (grp * 4) * SH1_STRIDE + h0;
        #pragma unroll 8
        for (int e = 0; e < ECH; e++) {
            unsigned long long w[5];
            #pragma unroll
            for (int r = 0; r < 5; r++)
                w[r] = *(const unsigned long long*)&sWc[e * HP + 2 * hl + 32 * r];
            #pragma unroll
            for (int jj = 0; jj < 4; jj++) {
                unsigned long long a = dup2(h1Row[jj * SH1_STRIDE + e]);
                #pragma unroll
                for (int r = 0; r < 5; r++) ffma2(acc[jj][r], a, w[r]);
            }
        }
    }

    // ================= epilogue 2: relu(+b2), dot W3, reduce =================
    float part[4];
    #pragma unroll
    for (int jj = 0; jj < 4; jj++) {
        float p = 0.f;
        #pragma unroll
        for (int r = 0; r < 5; r++) {
            int k = 2 * hl + 32 * r;
            float2 v = *(float2*)&acc[jj][r];
            float hx = fmaxf(v.x + sB2[k],     0.f);
            float hy = fmaxf(v.y + sB2[k + 1], 0.f);
            p = fmaf(hx, sW3[k], p);
            p = fmaf(hy, sW3[k + 1], p);
        }
        #pragma unroll
        for (int off = 8; off; off >>= 1)
            p += __shfl_xor_sync(0xffffffffu, p, off);   // stays in half-warp
        part[jj] = p;
    }

    if (hl == 0) {
        float bb3 = b3[0];
        float mi  = m[b * NN + i];
        #pragma unroll
        for (int jj = 0; jj < 4; jj++) {
            int j = jbase + grp * 4 + jj;
            out[((size_t)b * NN + i) * NN + j] =
                (mi + m[b * NN + j] + part[jj] + bb3) * (1.0f / 3.0f);
        }
    }
}

// ---------------------------------------------------------------------------
extern "C" void kernel_launch(void* const* d_in, const int* in_sizes, int n_in,
                              void* d_out, int out_size)
{
    const float* g  = (const float*)d_in[0];
    const float* m  = (const float*)d_in[1];
    const float* W1 = (const float*)d_in[2];
    const float* b1 = (const float*)d_in[3];
    const float* W2 = (const float*)d_in[4];
    const float* b2 = (const float*)d_in[5];
    const float* W3 = (const float*)d_in[6];
    const float* b3 = (const float*)d_in[7];
    float* out = (float*)d_out;

    static const int SMEM_BYTES =
        (ECH * HP + TJ * SPG_STRIDE + TJ * SH1_STRIDE + EE + 2 * HP) * 4;

    cudaFuncSetAttribute(pair_kernel,
                         cudaFuncAttributeMaxDynamicSharedMemorySize, SMEM_BYTES);

    pad_weights_kernel<<<(EE * HP + 255) / 256, 256>>>(W1, W2);
    row_proj_kernel<<<BB * NN, HP>>>(g, W1, b1);

    dim3 grid(NN / TJ, NN, BB);   // (4, 256, 2)
    pair_kernel<<<grid, NTHREADS, SMEM_BYTES>>>(g, m, b2, W3, b3, out);
}